// round 3
// baseline (speedup 1.0000x reference)
#include <cuda_runtime.h>
#include <cstdint>

#define BT_TOT 192
#define NN 64
#define DM 128
#define TT 96
#define SCOLS 320   // 0-127: G=Z@ (Wq Wk^T), 128-255: Vt=Z@(Wv Wth), 256-287: qh, 288-319: kh

__device__ float g_Wcat[128 * SCOLS];
__device__ float g_S1[12288 * SCOLS];

// ---------------- K0: fuse weights into g_Wcat ----------------
__global__ void k0_fuse(const float* __restrict__ Wq, const float* __restrict__ Wk,
                        const float* __restrict__ Wv, const float* __restrict__ W1,
                        const float* __restrict__ Wth) {
    __shared__ float rq[128], rk[128], rv[128];
    int k = blockIdx.x;
    int tid = threadIdx.x;  // 320 threads
    if (tid < 128) {
        rq[tid] = Wq[k * 128 + tid];
        rk[tid] = Wk[k * 128 + tid];
        rv[tid] = Wv[k * 128 + tid];
    }
    __syncthreads();
    int c = tid;
    float acc = 0.f;
    if (c < 128) {
        // Wqk[k][c] = sum_m Wq[k][m] * Wk[c][m]
        #pragma unroll 4
        for (int m = 0; m < 128; m++) acc += rq[m] * Wk[c * 128 + m];
    } else if (c < 256) {
        int cc = c - 128;
        #pragma unroll 4
        for (int m = 0; m < 128; m++) acc += rv[m] * Wth[m * 128 + cc];
    } else if (c < 288) {
        int t = c - 256;
        #pragma unroll 4
        for (int m = 0; m < 128; m++) acc += rq[m] * W1[m * 32 + t];
    } else {
        int t = c - 288;
        #pragma unroll 4
        for (int m = 0; m < 128; m++) acc += rk[m] * W1[(128 + m) * 32 + t];
    }
    g_Wcat[k * SCOLS + c] = acc;
}

// ---------------- K1: S1[12288,320] = Z[12288,128] @ Wcat[128,320] ----------------
// Z row r = (bt, n): ptr = x + ((b*64+n)*96 + t)*128, bt = r>>6, n = r&63, b=bt/96, t=bt%96
__global__ void __launch_bounds__(256) k1_gemm(const float* __restrict__ x) {
    __shared__ float As[128 * 32];
    __shared__ float Bs[32 * 128];
    int m0 = blockIdx.x * 128;
    int n0 = blockIdx.y * 128;
    int tid = threadIdx.x;
    int tx = tid & 15, ty = tid >> 4;
    float acc[8][8];
    #pragma unroll
    for (int u = 0; u < 8; u++)
        #pragma unroll
        for (int v = 0; v < 8; v++) acc[u][v] = 0.f;

    for (int kk = 0; kk < 128; kk += 32) {
        #pragma unroll
        for (int it = 0; it < 4; it++) {
            int idx = tid + it * 256;
            int i = idx >> 3, c4 = (idx & 7) * 4;
            int r = m0 + i;
            int bt = r >> 6, n = r & 63;
            int b = bt / 96, t = bt - b * 96;
            float4 v = *(const float4*)(x + (size_t)(((b * 64 + n) * 96 + t)) * 128 + kk + c4);
            *(float4*)(As + i * 32 + c4) = v;
        }
        #pragma unroll
        for (int it = 0; it < 4; it++) {
            int idx = tid + it * 256;
            int kr = idx >> 5, c4 = (idx & 31) * 4;
            int col = n0 + c4;
            float4 v = make_float4(0.f, 0.f, 0.f, 0.f);
            if (col < SCOLS) v = *(const float4*)(g_Wcat + (kk + kr) * SCOLS + col);
            *(float4*)(Bs + kr * 128 + c4) = v;
        }
        __syncthreads();
        #pragma unroll
        for (int k = 0; k < 32; k++) {
            float a[8], bb[8];
            #pragma unroll
            for (int u = 0; u < 8; u++) a[u] = As[(ty * 8 + u) * 32 + k];
            float4 b0 = *(float4*)(Bs + k * 128 + tx * 8);
            float4 b1 = *(float4*)(Bs + k * 128 + tx * 8 + 4);
            bb[0] = b0.x; bb[1] = b0.y; bb[2] = b0.z; bb[3] = b0.w;
            bb[4] = b1.x; bb[5] = b1.y; bb[6] = b1.z; bb[7] = b1.w;
            #pragma unroll
            for (int u = 0; u < 8; u++)
                #pragma unroll
                for (int v = 0; v < 8; v++) acc[u][v] = fmaf(a[u], bb[v], acc[u][v]);
        }
        __syncthreads();
    }
    if (n0 + tx * 8 < SCOLS) {
        #pragma unroll
        for (int u = 0; u < 8; u++) {
            int r = m0 + ty * 8 + u;
            *(float4*)(g_S1 + (size_t)r * SCOLS + n0 + tx * 8) =
                make_float4(acc[u][0], acc[u][1], acc[u][2], acc[u][3]);
            *(float4*)(g_S1 + (size_t)r * SCOLS + n0 + tx * 8 + 4) =
                make_float4(acc[u][4], acc[u][5], acc[u][6], acc[u][7]);
        }
    }
}

// ---------------- K2: fused attention per bt ----------------
__global__ void __launch_bounds__(256) k2_attn(
    const float* __restrict__ x, const float* __restrict__ edge,
    const float* __restrict__ prior, const unsigned char* __restrict__ maskp,
    const float* __restrict__ W1, const float* __restrict__ b1,
    const float* __restrict__ W2, const float* __restrict__ b2,
    const float* __restrict__ Wfuse, const float* __restrict__ lng,
    const float* __restrict__ lnb, const float* __restrict__ pw,
    const float* __restrict__ prw, float* __restrict__ out) {
    extern __shared__ float sm[];
    float* Zs   = sm;               // 64*132
    float* Gs   = Zs + 64 * 132;    // 64*132 (reused as h in phase D/E)
    float* Vs   = Gs + 64 * 132;    // 64*128
    float* qhs  = Vs + 64 * 128;    // 64*32   (reused: alphaT = qhs, 64*68)
    float* khs  = qhs + 64 * 32;    // 64*36
    float* Ls   = khs + 64 * 36;    // 64*64
    float* W1eT = Ls + 64 * 64;     // 32*4
    float* b1s  = W1eT + 128;       // 32
    float* W2s  = b1s + 32;         // 32
    float* lngs = W2s + 32;         // 128
    float* lnbs = lngs + 128;       // 128
    float* Wfs  = lnbs + 128;       // 8
    float* msk  = Wfs + 8;          // 64
    float* alphaT = qhs;            // 64*68 overlay (qhs+khs = 4352 floats)

    int bt = blockIdx.x;
    int b = bt / 96, t = bt - b * 96;
    int tid = threadIdx.x;
    int warp = tid >> 5, lane = tid & 31;

    // ---- Phase A: loads ----
    const float* xbase = x + (size_t)((b * 64) * 96 + t) * 128;
    const float* s1 = g_S1 + (size_t)(bt * 64) * SCOLS;
    #pragma unroll
    for (int it = 0; it < 8; it++) {
        int idx = tid + it * 256;
        int i = idx >> 5, c4 = (idx & 31) * 4;
        *(float4*)(Zs + i * 132 + c4) = *(const float4*)(xbase + (size_t)i * 96 * 128 + c4);
        *(float4*)(Gs + i * 132 + c4) = *(const float4*)(s1 + (size_t)i * SCOLS + c4);
        *(float4*)(Vs + i * 128 + c4) = *(const float4*)(s1 + (size_t)i * SCOLS + 128 + c4);
    }
    #pragma unroll
    for (int it = 0; it < 2; it++) {
        int idx = tid + it * 256;
        int i = idx >> 3, c4 = (idx & 7) * 4;
        *(float4*)(qhs + i * 32 + c4) = *(const float4*)(s1 + (size_t)i * SCOLS + 256 + c4);
        *(float4*)(khs + i * 36 + c4) = *(const float4*)(s1 + (size_t)i * SCOLS + 288 + c4);
    }
    if (tid < 128) {
        int tt = tid >> 2, c = tid & 3;
        W1eT[tt * 4 + c] = W1[(256 + c) * 32 + tt];
        lngs[tid] = lng[tid];
        lnbs[tid] = lnb[tid];
    }
    if (tid < 32) { b1s[tid] = b1[tid]; W2s[tid] = W2[tid]; }
    if (tid < 5) Wfs[tid] = Wfuse[tid];
    if (tid < 64) msk[tid] = (float)maskp[b * 64 + tid];
    __syncthreads();

    float pwv = pw[0], prwv = prw[0], b2v = b2[0];

    // ---- Phase B: logits ----
    const float* ebase = edge + (size_t)bt * 4096 * 4;
    const float* pbase = prior + (size_t)bt * 4096 * 5;
    int ib = tid >> 6;      // 0..3
    int j = tid & 63;
    #pragma unroll 1
    for (int ii = 0; ii < 16; ii++) {
        int i = ib + ii * 4;
        // content: G_i . Z_j
        float cx = 0.f, cy = 0.f, cz = 0.f, cw = 0.f;
        #pragma unroll
        for (int d4 = 0; d4 < 128; d4 += 4) {
            float4 g = *(float4*)(Gs + i * 132 + d4);
            float4 z = *(float4*)(Zs + j * 132 + d4);
            cx = fmaf(g.x, z.x, cx); cy = fmaf(g.y, z.y, cy);
            cz = fmaf(g.z, z.z, cz); cw = fmaf(g.w, z.w, cw);
        }
        float content = (cx + cy + cz + cw) * 0.08838834764831845f;  // 1/sqrt(128)
        // edge MLP
        float4 e = *(const float4*)(ebase + (size_t)(i * 64 + j) * 4);
        float phys = 0.f;
        #pragma unroll
        for (int t4 = 0; t4 < 32; t4 += 4) {
            float4 khv = *(float4*)(khs + j * 36 + t4);
            float4 qhv = *(float4*)(qhs + i * 32 + t4);
            float4 bv  = *(float4*)(b1s + t4);
            float4 wv  = *(float4*)(W2s + t4);
            float4 w0 = *(float4*)(W1eT + (t4 + 0) * 4);
            float4 w1 = *(float4*)(W1eT + (t4 + 1) * 4);
            float4 w2 = *(float4*)(W1eT + (t4 + 2) * 4);
            float4 w3 = *(float4*)(W1eT + (t4 + 3) * 4);
            float h;
            h = qhv.x + khv.x + bv.x + e.x*w0.x + e.y*w0.y + e.z*w0.z + e.w*w0.w;
            phys = fmaf(fmaxf(h, 0.f), wv.x, phys);
            h = qhv.y + khv.y + bv.y + e.x*w1.x + e.y*w1.y + e.z*w1.z + e.w*w1.w;
            phys = fmaf(fmaxf(h, 0.f), wv.y, phys);
            h = qhv.z + khv.z + bv.z + e.x*w2.x + e.y*w2.y + e.z*w2.z + e.w*w2.w;
            phys = fmaf(fmaxf(h, 0.f), wv.z, phys);
            h = qhv.w + khv.w + bv.w + e.x*w3.x + e.y*w3.y + e.z*w3.z + e.w*w3.w;
            phys = fmaf(fmaxf(h, 0.f), wv.w, phys);
        }
        phys += b2v;
        // prior
        const float* ap = pbase + (size_t)(i * 64 + j) * 5;
        float Ap = ap[0]*Wfs[0] + ap[1]*Wfs[1] + ap[2]*Wfs[2] + ap[3]*Wfs[3] + ap[4]*Wfs[4];
        Ap = fmaxf(Ap, 0.f);
        float L = content + pwv * phys + prwv * logf(Ap + 1e-6f);
        if (msk[i] != 0.f || msk[j] != 0.f) L = -1e9f;
        Ls[i * 64 + j] = L;
    }
    __syncthreads();

    // ---- Phase C: softmax per row, write transposed alpha ----
    #pragma unroll 1
    for (int rr = 0; rr < 8; rr++) {
        int r = warp + rr * 8;
        float v0 = Ls[r * 64 + lane], v1 = Ls[r * 64 + lane + 32];
        float m = fmaxf(v0, v1);
        #pragma unroll
        for (int o = 16; o; o >>= 1) m = fmaxf(m, __shfl_xor_sync(0xffffffffu, m, o));
        float e0 = expf(v0 - m), e1 = expf(v1 - m);
        float s = e0 + e1;
        #pragma unroll
        for (int o = 16; o; o >>= 1) s += __shfl_xor_sync(0xffffffffu, s, o);
        float inv = 1.f / s;
        alphaT[lane * 68 + r] = e0 * inv;
        alphaT[(lane + 32) * 68 + r] = e1 * inv;
    }
    __syncthreads();

    // ---- Phase D: h = Z + alpha @ Vt ----
    int di = tid & 127, half = tid >> 7;
    #pragma unroll 1
    for (int it = 0; it < 4; it++) {
        int i0 = half * 32 + it * 8;
        float acc[8];
        #pragma unroll
        for (int u = 0; u < 8; u++) acc[u] = Zs[(i0 + u) * 132 + di];
        #pragma unroll 4
        for (int jj = 0; jj < 64; jj++) {
            float vv = Vs[jj * 128 + di];
            float4 a0 = *(float4*)(alphaT + jj * 68 + i0);
            float4 a1 = *(float4*)(alphaT + jj * 68 + i0 + 4);
            acc[0] = fmaf(a0.x, vv, acc[0]); acc[1] = fmaf(a0.y, vv, acc[1]);
            acc[2] = fmaf(a0.z, vv, acc[2]); acc[3] = fmaf(a0.w, vv, acc[3]);
            acc[4] = fmaf(a1.x, vv, acc[4]); acc[5] = fmaf(a1.y, vv, acc[5]);
            acc[6] = fmaf(a1.z, vv, acc[6]); acc[7] = fmaf(a1.w, vv, acc[7]);
        }
        #pragma unroll
        for (int u = 0; u < 8; u++) Gs[(i0 + u) * 132 + di] = acc[u];
    }
    __syncthreads();

    // ---- Phase E: LayerNorm + masked, transposed store ----
    float* outb = out + (size_t)((b * 64) * 96 + t) * 128;
    #pragma unroll 1
    for (int rr = 0; rr < 8; rr++) {
        int r = warp + rr * 8;
        float v[4];
        #pragma unroll
        for (int u = 0; u < 4; u++) v[u] = Gs[r * 132 + lane + 32 * u];
        float s = v[0] + v[1] + v[2] + v[3];
        #pragma unroll
        for (int o = 16; o; o >>= 1) s += __shfl_xor_sync(0xffffffffu, s, o);
        float mu = s * (1.f / 128.f);
        float q = 0.f;
        #pragma unroll
        for (int u = 0; u < 4; u++) { float d = v[u] - mu; q = fmaf(d, d, q); }
        #pragma unroll
        for (int o = 16; o; o >>= 1) q += __shfl_xor_sync(0xffffffffu, q, o);
        float inv = rsqrtf(q * (1.f / 128.f) + 1e-5f);
        float keep = (msk[r] != 0.f) ? 0.f : 1.f;
        float* op = outb + (size_t)r * 96 * 128;
        #pragma unroll
        for (int u = 0; u < 4; u++) {
            int d = lane + 32 * u;
            op[d] = ((v[u] - mu) * inv * lngs[d] + lnbs[d]) * keep;
        }
    }
}

extern "C" void kernel_launch(void* const* d_in, const int* in_sizes, int n_in,
                              void* d_out, int out_size) {
    const float* x     = (const float*)d_in[0];
    const float* edge  = (const float*)d_in[1];
    const float* prior = (const float*)d_in[2];
    const unsigned char* maskp = (const unsigned char*)d_in[3];
    const float* Wq    = (const float*)d_in[4];
    const float* Wk    = (const float*)d_in[5];
    const float* Wv    = (const float*)d_in[6];
    const float* W1    = (const float*)d_in[7];
    const float* b1    = (const float*)d_in[8];
    const float* W2    = (const float*)d_in[9];
    const float* b2    = (const float*)d_in[10];
    const float* Wfuse = (const float*)d_in[11];
    const float* Wth   = (const float*)d_in[12];
    const float* lng   = (const float*)d_in[13];
    const float* lnb   = (const float*)d_in[14];
    const float* pw    = (const float*)d_in[15];
    const float* prw   = (const float*)d_in[16];
    float* out = (float*)d_out;

    const int smem2 = (64*132 + 64*132 + 64*128 + 64*32 + 64*36 + 64*64
                       + 128 + 32 + 32 + 128 + 128 + 8 + 64) * sizeof(float);
    cudaFuncSetAttribute(k2_attn, cudaFuncAttributeMaxDynamicSharedMemorySize, smem2);

    k0_fuse<<<128, 320>>>(Wq, Wk, Wv, W1, Wth);
    k1_gemm<<<dim3(96, 3), 256>>>(x);
    k2_attn<<<192, 256, smem2>>>(x, edge, prior, maskp, W1, b1, W2, b2,
                                 Wfuse, lng, lnb, pw, prw, out);
}